// round 17
// baseline (speedup 1.0000x reference)
#include <cuda_runtime.h>
#include <cuda_bf16.h>
#include <cstdint>
#include <cstddef>

#define BSZ  64
#define TT   512
#define FEAT 1024
#define HID  1024
#define H3   3072

#define XCHK 64     // xproj k-chunk
#define XS   68     // xproj smem row stride

#define AST2 516    // recur staged-A row stride (u32), conflict-free
#define SR   18     // recur per-warp reduce row stride
#define REDW (32*SR)
#define SF   20     // final reduce row stride

// Scratch for x-projections: pre[m][n]
__device__ float g_pre[(size_t)BSZ * TT * H3];
// bf16 shadow state: h and (r.*h)  [64 rows][1024]
__device__ __nv_bfloat16 g_hb [(size_t)BSZ * HID];
__device__ __nv_bfloat16 g_rhb[(size_t)BSZ * HID];

// barrier state: per-block epoch flags (one 128B line each) + init barrier
__device__ __align__(128) unsigned g_flags[256 * 32];
__device__ __align__(128) unsigned g_icount[32];
__device__ __align__(128) unsigned g_igen[32];

// ---------- helpers ----------
__device__ __forceinline__ float sigmoidf_(float v) {
    return 1.0f / (1.0f + expf(-v));
}
__device__ __forceinline__ uint32_t cvt_tf32(float x) {
    uint32_t r;
    asm("cvt.rna.tf32.f32 %0, %1;" : "=r"(r) : "f"(x));
    return r;
}
__device__ __forceinline__ uint32_t pack_bf16(float lo, float hi) {
    __nv_bfloat162 v = __floats2bfloat162_rn(lo, hi);
    return *reinterpret_cast<uint32_t*>(&v);
}
__device__ __forceinline__ void mma_tf32(float* c, const uint32_t* a,
                                         const uint32_t* b) {
    asm volatile(
        "mma.sync.aligned.m16n8k8.row.col.f32.tf32.tf32.f32 "
        "{%0,%1,%2,%3}, {%4,%5,%6,%7}, {%8,%9}, {%0,%1,%2,%3};"
        : "+f"(c[0]), "+f"(c[1]), "+f"(c[2]), "+f"(c[3])
        : "r"(a[0]), "r"(a[1]), "r"(a[2]), "r"(a[3]),
          "r"(b[0]), "r"(b[1]));
}
__device__ __forceinline__ void mma_bf16(float* c, const uint32_t* a,
                                         const uint32_t* b) {
    asm volatile(
        "mma.sync.aligned.m16n8k16.row.col.f32.bf16.bf16.f32 "
        "{%0,%1,%2,%3}, {%4,%5,%6,%7}, {%8,%9}, {%0,%1,%2,%3};"
        : "+f"(c[0]), "+f"(c[1]), "+f"(c[2]), "+f"(c[3])
        : "r"(a[0]), "r"(a[1]), "r"(a[2]), "r"(a[3]),
          "r"(b[0]), "r"(b[1]));
}
// ldmatrix x4: full m16xk16 bf16 A-fragment in one instruction
__device__ __forceinline__ void ldsm4(uint32_t* a, uint32_t saddr) {
    asm volatile(
        "ldmatrix.sync.aligned.m8n8.x4.shared.b16 {%0,%1,%2,%3}, [%4];"
        : "=r"(a[0]), "=r"(a[1]), "=r"(a[2]), "=r"(a[3]) : "r"(saddr));
}
__device__ __forceinline__ unsigned ld_acq(const unsigned* p) {
    unsigned v;
    asm volatile("ld.acquire.gpu.global.u32 %0, [%1];" : "=r"(v) : "l"(p));
    return v;
}
__device__ __forceinline__ void st_rel(unsigned* p, unsigned v) {
    asm volatile("st.release.gpu.global.u32 [%0], %1;" :: "l"(p), "r"(v));
}
__device__ __forceinline__ void cpasync16(uint32_t saddr, const void* gaddr) {
    asm volatile("cp.async.cg.shared.global [%0], [%1], 16;"
                 :: "r"(saddr), "l"(gaddr));
}
__device__ __forceinline__ void cpcommit() {
    asm volatile("cp.async.commit_group;");
}
template <int N> __device__ __forceinline__ void cpwait() {
    asm volatile("cp.async.wait_group %0;" :: "n"(N));
}

// ---------- bulk-copy (UBLKCP) staging ----------
__device__ __forceinline__ void cpbulk(uint32_t sdst, const void* gsrc,
                                       unsigned bytes, uint32_t mbar) {
    asm volatile(
        "cp.async.bulk.shared::cta.global.mbarrier::complete_tx::bytes "
        "[%0], [%1], %2, [%3];"
        :: "r"(sdst), "l"(gsrc), "r"(bytes), "r"(mbar) : "memory");
}
__device__ __forceinline__ void mbar_init(uint32_t mbar, unsigned cnt) {
    asm volatile("mbarrier.init.shared.b64 [%0], %1;" :: "r"(mbar), "r"(cnt)
                 : "memory");
}
__device__ __forceinline__ void mbar_expect(uint32_t mbar, unsigned bytes) {
    asm volatile("mbarrier.arrive.expect_tx.shared.b64 _, [%0], %1;"
                 :: "r"(mbar), "r"(bytes) : "memory");
}
__device__ __forceinline__ void mbar_wait(uint32_t mbar, unsigned parity) {
    asm volatile(
        "{\n\t.reg .pred P;\n\t"
        "W0_%=:\n\t"
        "mbarrier.try_wait.parity.acquire.cta.shared::cta.b64 P, [%0], %1, 0x989680;\n\t"
        "@P bra W1_%=;\n\t"
        "bra W0_%=;\n\t"
        "W1_%=:\n\t}"
        :: "r"(mbar), "r"(parity) : "memory");
}

// atomic sense-reversing barrier (init only; replay-safe)
__device__ __forceinline__ void swsync(unsigned* cnt, unsigned* gen, int n) {
    __syncthreads();
    if (threadIdx.x == 0) {
        __threadfence();
        const unsigned my = ld_acq(gen);
        if (atomicAdd(cnt, 1) == (unsigned)(n - 1)) {
            *cnt = 0;
            st_rel(gen, my + 1);
        } else {
            while (ld_acq(gen) == my) { }
        }
    }
    __syncthreads();
}

extern __shared__ float smem_dyn[];

// =====================================================================
// Kernel 1: x projections (tf32 mma.sync) — unchanged.
// =====================================================================
__global__ __launch_bounds__(256) void xproj_kernel(
    const float* __restrict__ x,
    const float* __restrict__ wz, const float* __restrict__ wr,
    const float* __restrict__ wh,
    const float* __restrict__ bz, const float* __restrict__ br,
    const float* __restrict__ bh, int m_off)
{
    float* sx  = smem_dyn;                 // [2][64][XS]
    float* swt = smem_dyn + 2 * 64 * XS;   // [2][64][XS]

    const int tid = threadIdx.x;
    const int n0  = blockIdx.x * 64;
    const int m0  = (m_off + blockIdx.y) * 64;

    const int gate = n0 >> 10;
    const int ng   = n0 & 1023;
    const float* wptr = (gate == 0) ? wz : (gate == 1) ? wr : wh;
    const float* bptr = (gate == 0) ? bz : (gate == 1) ? br : bh;

    const int w  = tid >> 5;
    const int l  = tid & 31;
    const int kw = w >> 2;
    const int mw = (w >> 1) & 1;
    const int nw = w & 1;

    float c[2][4][4];
#pragma unroll
    for (int mt = 0; mt < 2; mt++)
#pragma unroll
        for (int nt = 0; nt < 4; nt++)
#pragma unroll
            for (int r = 0; r < 4; r++) c[mt][nt][r] = 0.0f;

    const int s_row = tid >> 4;
    const int s_q   = tid & 15;

    auto stage = [&](int buf, int k0) {
#pragma unroll
        for (int i = 0; i < 4; i++) {
            int row = s_row + 16 * i;
            uint32_t sa = (uint32_t)__cvta_generic_to_shared(
                sx + buf * 64 * XS + row * XS + 4 * s_q);
            cpasync16(sa, x + (size_t)(m0 + row) * FEAT + k0 + 4 * s_q);
        }
#pragma unroll
        for (int i = 0; i < 4; i++) {
            int kr = s_row + 16 * i;
            uint32_t sa = (uint32_t)__cvta_generic_to_shared(
                swt + buf * 64 * XS + kr * XS + 4 * s_q);
            cpasync16(sa, wptr + (size_t)(1024 + k0 + kr) * HID + ng + 4 * s_q);
        }
        cpcommit();
    };

    const int ar = l >> 2, ac = l & 3;
    const int bk = l & 3,  bn = l >> 2;

    stage(0, 0);
    for (int ch = 0; ch < FEAT / XCHK; ch++) {
        if (ch + 1 < FEAT / XCHK) {
            stage((ch + 1) & 1, (ch + 1) * XCHK);
            cpwait<1>();
        } else {
            cpwait<0>();
        }
        __syncthreads();

        const float* SX = sx  + (ch & 1) * 64 * XS;
        const float* SW = swt + (ch & 1) * 64 * XS;

#pragma unroll
        for (int kt = 0; kt < 4; kt++) {
            const int k = kw * 32 + kt * 8;

            uint32_t a[2][4];
#pragma unroll
            for (int mt = 0; mt < 2; mt++) {
                const float* P = SX + (mw * 32 + mt * 16 + ar) * XS + k + ac;
                a[mt][0] = cvt_tf32(P[0]);
                a[mt][1] = cvt_tf32(P[8 * XS]);
                a[mt][2] = cvt_tf32(P[4]);
                a[mt][3] = cvt_tf32(P[8 * XS + 4]);
            }
            uint32_t b[4][2];
#pragma unroll
            for (int nt = 0; nt < 4; nt++) {
                const float* Q = SW + (k + bk) * XS + nw * 32 + nt * 8 + bn;
                b[nt][0] = cvt_tf32(Q[0]);
                b[nt][1] = cvt_tf32(Q[4 * XS]);
            }
#pragma unroll
            for (int mt = 0; mt < 2; mt++)
#pragma unroll
                for (int nt = 0; nt < 4; nt++)
                    mma_tf32(c[mt][nt], a[mt], b[nt]);
        }
        __syncthreads();
    }

    float* sred = smem_dyn;
    if (kw == 1) {
        float* dst = sred + (mw * 2 + nw) * 1024;
#pragma unroll
        for (int mt = 0; mt < 2; mt++)
#pragma unroll
            for (int nt = 0; nt < 4; nt++)
#pragma unroll
                for (int r = 0; r < 4; r++) {
                    int row = mt * 16 + (l >> 2) + (r >= 2 ? 8 : 0);
                    int col = nt * 8 + 2 * (l & 3) + (r & 1);
                    dst[row * 32 + col] = c[mt][nt][r];
                }
    }
    __syncthreads();
    if (kw == 0) {
        const float* src = sred + (mw * 2 + nw) * 1024;
#pragma unroll
        for (int mt = 0; mt < 2; mt++)
#pragma unroll
            for (int nt = 0; nt < 4; nt++) {
#pragma unroll
                for (int r = 0; r < 4; r++) {
                    int row = mt * 16 + (l >> 2) + (r >= 2 ? 8 : 0);
                    int col = nt * 8 + 2 * (l & 3) + (r & 1);
                    c[mt][nt][r] += src[row * 32 + col];
                }
#pragma unroll
                for (int half = 0; half < 2; half++) {
                    const int row = mt * 16 + (l >> 2) + 8 * half;
                    const int nbase = nw * 32 + nt * 8 + 2 * (l & 3);
                    float2 v;
                    v.x = c[mt][nt][2 * half + 0] + bptr[ng + nbase];
                    v.y = c[mt][nt][2 * half + 1] + bptr[ng + nbase + 1];
                    *(float2*)&g_pre[(size_t)(m0 + mw * 32 + row) * H3 + n0 + nbase] = v;
                }
            }
    }
}

// =====================================================================
// Kernel 2: persistent recurrence — 2 blocks/SM (HW-interleaved halves).
// 256 blocks x 256 threads; block = 8 cols x one batch half (32 rows).
// half = bid>=128 (placement pairs bid,bid+148 on one SM -> mixed halves).
// Per-half barrier over 128 blocks; while one block waits, its SM-mate
// (other half) computes.  Phase A: r+z.  Phase B: hbar.
// =====================================================================
__global__ __launch_bounds__(256, 2) void recur_kernel(
    const float* __restrict__ h0,
    const float* __restrict__ wz, const float* __restrict__ wr,
    const float* __restrict__ wh,
    float* __restrict__ out)
{
    uint32_t* sA   = (uint32_t*)smem_dyn;           // [32][AST2]
    float*    sred = smem_dyn + 32 * AST2;          // [8][32][SR]
    float*    sfin = sred + 8 * REDW;               // [32][SF]
    uint64_t* mb   = (uint64_t*)(sfin + 32 * SF);   // 1 mbarrier

    const int tid  = threadIdx.x;
    const int w    = tid >> 5;
    const int l    = tid & 31;
    const int half = (blockIdx.x >> 7) & 1;    // bid<128 -> half0
    const int cg   = blockIdx.x & 127;         // 0..127
    const int j0   = cg * 8;

    const uint32_t mbar = (uint32_t)__cvta_generic_to_shared(mb);
    const uint32_t sAu  = (uint32_t)__cvta_generic_to_shared(sA);

    const int bk = l & 3,  bn = l >> 2;       // B-frag coords (n=8)

    // ldmatrix per-lane address offset within buffer
    const int rowsel = (l & 7) + 8 * ((l >> 3) & 1);
    const int colsel = 4 * (l >> 4);
    const uint32_t aoff0 = (uint32_t)((rowsel * AST2 + colsel) * 4);
    const uint32_t aoff1 = aoff0 + 16 * AST2 * 4;

    // ---- one-time: bf16 B fragments (k-slice 128w, n=8) ----
    uint32_t bzf[8][2], brf[8][2], bhf[8][2];
#pragma unroll
    for (int kt = 0; kt < 8; kt++)
#pragma unroll
        for (int h = 0; h < 2; h++) {
            const int k0 = 128 * w + 16 * kt + 2 * bk + 8 * h;
            const int n  = j0 + bn;
            bzf[kt][h] = pack_bf16(wz[(size_t)k0 * HID + n], wz[(size_t)(k0 + 1) * HID + n]);
            brf[kt][h] = pack_bf16(wr[(size_t)k0 * HID + n], wr[(size_t)(k0 + 1) * HID + n]);
            bhf[kt][h] = pack_bf16(wh[(size_t)k0 * HID + n], wh[(size_t)(k0 + 1) * HID + n]);
        }

    // ---- one-time: flag reset, mbarrier, h0 -> bf16, init barrier ----
    if (tid == 0) {
        g_flags[blockIdx.x * 32] = 0;
        mbar_init(mbar, 1);
    }
    {
        const int idx = blockIdx.x * 256 + tid;    // 65536 elems
        g_hb[idx] = __float2bfloat16(h0[idx]);
    }
    swsync(&g_icount[0], &g_igen[0], 256);

    // flag-array barrier over this half's 128 blocks
    unsigned ep = 0;
    auto fsync = [&]() {
        __syncthreads();
        ep++;
        if (tid == 0) {
            __threadfence();
            st_rel(&g_flags[blockIdx.x * 32], ep);
        }
        if (tid < 128) {
            const unsigned* f = &g_flags[(half * 128 + tid) * 32];
            while (ld_acq(f) < ep) { }
        }
        __syncthreads();
    };

    // bulk-stage this half's 32x1024 bf16 rows (64KB)
    unsigned mpar = 0;
    auto stage_bulk = [&](const __nv_bfloat16* src) {
        if (tid == 0) {
            mbar_expect(mbar, 32 * 2048);
            const __nv_bfloat16* base = src + (size_t)half * 32 * HID;
#pragma unroll
            for (int row = 0; row < 32; row++)
                cpbulk(sAu + row * (AST2 * 4), base + (size_t)row * HID,
                       2048, mbar);
        }
    };

    // elementwise mapping: 1 output/thread
    const int eb = tid >> 3;                   // 0..31
    const int ec = tid & 7;                    // 0..7
    const int gb = half * 32 + eb;

    for (int t = 0; t < TT; t++) {
        const float* hprev = (t == 0) ? h0 : (out + (size_t)(t - 1) * HID);
        const long   hstr  = (t == 0) ? (long)HID : (long)TT * HID;

        // ---- stage h ----
        stage_bulk(g_hb);

        // pointwise prefetch
        const float* pp = g_pre + (size_t)(gb * TT + t) * H3 + j0 + ec;
        const float xz = __ldg(pp);
        const float xr = __ldg(pp + 1024);
        const float xh = __ldg(pp + 2048);
        const float hp = __ldcg(hprev + (size_t)gb * hstr + j0 + ec);

        // ================= phase A: r + z =================
        float aR[2][4], aZ[2][4];
#pragma unroll
        for (int mt = 0; mt < 2; mt++)
#pragma unroll
            for (int r = 0; r < 4; r++) { aR[mt][r] = 0.0f; aZ[mt][r] = 0.0f; }

        mbar_wait(mbar, mpar);  mpar ^= 1;

#pragma unroll
        for (int mt = 0; mt < 2; mt++)
#pragma unroll
            for (int kt = 0; kt < 8; kt++) {
                uint32_t a[4];
                ldsm4(a, sAu + (mt ? aoff1 : aoff0) + (64 * w + 8 * kt) * 4);
                mma_bf16(aR[mt], a, brf[kt]);
                mma_bf16(aZ[mt], a, bzf[kt]);
            }

        // k-split reduce: r -> cols 0..7, z -> cols 8..15
        {
            float* dst = sred + w * REDW;
#pragma unroll
            for (int mt = 0; mt < 2; mt++) {
                int r0 = 16 * mt + (l >> 2);
                int c0 = 2 * (l & 3);
                dst[r0 * SR + c0]           = aR[mt][0];
                dst[r0 * SR + c0 + 1]       = aR[mt][1];
                dst[(r0 + 8) * SR + c0]     = aR[mt][2];
                dst[(r0 + 8) * SR + c0 + 1] = aR[mt][3];
                dst[r0 * SR + 8 + c0]           = aZ[mt][0];
                dst[r0 * SR + 8 + c0 + 1]       = aZ[mt][1];
                dst[(r0 + 8) * SR + 8 + c0]     = aZ[mt][2];
                dst[(r0 + 8) * SR + 8 + c0 + 1] = aZ[mt][3];
            }
        }
        __syncthreads();
#pragma unroll
        for (int i = 0; i < 2; i++) {
            int idx = tid + i * 256;           // 512 = 32 rows x 16 cols
            int b = idx >> 4, n = idx & 15;
            float s = 0.0f;
#pragma unroll
            for (int ww = 0; ww < 8; ww++) s += sred[ww * REDW + b * SR + n];
            sfin[b * SF + n] = s;
        }
        __syncthreads();

        // elementwise A: z kept in reg, rh -> global
        const float zg = sigmoidf_(sfin[eb * SF + 8 + ec] + xz);
        {
            const float r = sigmoidf_(sfin[eb * SF + ec] + xr);
            g_rhb[(size_t)gb * HID + j0 + ec] = __float2bfloat16(r * hp);
        }

        fsync();   // rh complete (this half, 128 blocks)

        // ================= phase B: hbar =================
        stage_bulk(g_rhb);

        float aH[2][4];
#pragma unroll
        for (int mt = 0; mt < 2; mt++)
#pragma unroll
            for (int r = 0; r < 4; r++) aH[mt][r] = 0.0f;

        mbar_wait(mbar, mpar);  mpar ^= 1;

#pragma unroll
        for (int mt = 0; mt < 2; mt++)
#pragma unroll
            for (int kt = 0; kt < 8; kt++) {
                uint32_t a[4];
                ldsm4(a, sAu + (mt ? aoff1 : aoff0) + (64 * w + 8 * kt) * 4);
                mma_bf16(aH[mt], a, bhf[kt]);
            }

        // reduce hbar -> cols 0..7
        {
            float* dst = sred + w * REDW;
#pragma unroll
            for (int mt = 0; mt < 2; mt++) {
                int r0 = 16 * mt + (l >> 2);
                int c0 = 2 * (l & 3);
                dst[r0 * SR + c0]           = aH[mt][0];
                dst[r0 * SR + c0 + 1]       = aH[mt][1];
                dst[(r0 + 8) * SR + c0]     = aH[mt][2];
                dst[(r0 + 8) * SR + c0 + 1] = aH[mt][3];
            }
        }
        __syncthreads();
        {
            int b = tid >> 3, n = tid & 7;     // 256 = 32 rows x 8 cols
            float s = 0.0f;
#pragma unroll
            for (int ww = 0; ww < 8; ww++) s += sred[ww * REDW + b * SR + n];
            sfin[b * SF + n] = s;
        }
        __syncthreads();

        // elementwise B + output
        {
            const float hb = tanhf(sfin[eb * SF + ec] + xh);
            const float hn = (1.0f - zg) * hp + zg * hb;
            out[((size_t)gb * TT + t) * HID + j0 + ec] = hn;
            g_hb[(size_t)gb * HID + j0 + ec] = __float2bfloat16(hn);
            if (t == TT - 1)
                out[(size_t)BSZ * TT * HID + (size_t)gb * HID + j0 + ec] = hn;
        }

        if (t + 1 < TT)
            fsync();   // h complete (this half)
    }
}

// =====================================================================
extern "C" void kernel_launch(void* const* d_in, const int* in_sizes, int n_in,
                              void* d_out, int out_size)
{
    const float* x  = (const float*)d_in[0];
    const float* h0 = (const float*)d_in[1];
    const float* wz = (const float*)d_in[2];
    const float* wr = (const float*)d_in[3];
    const float* wh = (const float*)d_in[4];
    const float* bz = (const float*)d_in[5];
    const float* br = (const float*)d_in[6];
    const float* bh = (const float*)d_in[7];
    float* out = (float*)d_out;

    const int x_smem = 4 * 64 * XS * sizeof(float);
    const int r_smem = (32 * AST2 + 8 * REDW + 32 * SF) * sizeof(float) + 16;
    static bool attr_set = false;
    if (!attr_set) {
        cudaFuncSetAttribute(xproj_kernel,
                             cudaFuncAttributeMaxDynamicSharedMemorySize, x_smem);
        cudaFuncSetAttribute(recur_kernel,
                             cudaFuncAttributeMaxDynamicSharedMemorySize, r_smem);
        attr_set = true;
    }

    const int ysplit[4] = {0, 171, 342, 512};
    for (int s = 0; s < 3; s++) {
        dim3 g1(H3 / 64, ysplit[s + 1] - ysplit[s]);
        xproj_kernel<<<g1, 256, x_smem>>>(x, wz, wr, wh, bz, br, bh, ysplit[s]);
    }

    recur_kernel<<<256, 256, r_smem>>>(h0, wz, wr, wh, out);
}